// round 6
// baseline (speedup 1.0000x reference)
#include <cuda_runtime.h>
#include <cstdint>

#define LDIM 1024   // h*w
#define CDIM 256
#define BATCH 8

// Scratch (no cudaMalloc allowed)
__device__ float g_qkv[BATCH * 3 * CDIM * LDIM];
__device__ float g_attn[BATCH * CDIM * LDIM];

// ---------- packed f32x2 helpers ----------
__device__ __forceinline__ uint64_t pack2(float x, float y) {
    uint64_t r; asm("mov.b64 %0, {%1, %2};" : "=l"(r) : "f"(x), "f"(y)); return r;
}
__device__ __forceinline__ uint64_t dup2(float x) {
    uint64_t r; asm("mov.b64 %0, {%1, %1};" : "=l"(r) : "f"(x)); return r;
}
__device__ __forceinline__ uint64_t ffma2(uint64_t a, uint64_t b, uint64_t c) {
    uint64_t d; asm("fma.rn.f32x2 %0, %1, %2, %3;" : "=l"(d) : "l"(a), "l"(b), "l"(c)); return d;
}
__device__ __forceinline__ float2 unpack2(uint64_t v) {
    float2 f; asm("mov.b64 {%0, %1}, %2;" : "=f"(f.x), "=f"(f.y) : "l"(v)); return f;
}
__device__ __forceinline__ float ex2(float x) {
    float r; asm("ex2.approx.f32 %0, %1;" : "=f"(r) : "f"(x)); return r;
}
__device__ __forceinline__ void cp16(uint32_t smem, const void* gmem) {
    asm volatile("cp.async.ca.shared.global [%0], [%1], 16;" :: "r"(smem), "l"(gmem));
}
__device__ __forceinline__ void cp_commit() { asm volatile("cp.async.commit_group;"); }
template<int N> __device__ __forceinline__ void cp_wait() {
    asm volatile("cp.async.wait_group %0;" :: "n"(N));
}

// ---------------------------------------------------------------------------
// 1x1-conv GEMM: out[b][o][l] = sum_c W[o][c]*X[b][c][l] + bias[o] (+resid)
// Tile 64(o) x 128(l), k-step 16, 256 threads, microtile 4o x (2+2)l-pairs.
// As dup'd float2 (zero inner-loop MOVs), Bs via cp.async double-buffer.
// smem 32KB, regs ~85 -> 3 CTAs/SM.
// ---------------------------------------------------------------------------
template<bool RES>
__global__ __launch_bounds__(256, 3)
void gemm1x1(const float* __restrict__ W, const float* __restrict__ X,
             const float* __restrict__ bias, const float* __restrict__ resid,
             float* __restrict__ out, int M)
{
    __shared__ __align__(16) float2 As[2][16][64];   // [stage][k][o] dup'd, 16KB
    __shared__ __align__(16) float  Bs[2][16][128];  // [stage][k][l], 16KB

    const int b  = blockIdx.z;
    const int o0 = blockIdx.y * 64;
    const int l0 = blockIdx.x * 128;
    const int t  = threadIdx.x;
    const int tx = t & 15, ty = t >> 4;

    const float* Xb = X + (size_t)b * CDIM * LDIM;

    // A ldg mapping: t -> (o row, k quad). Warp = 8 o-rows x 64B contiguous.
    const int ao  = t >> 2;          // 0..63
    const int akq = (t & 3) * 4;     // 0,4,8,12
    const float* wptr = W + (size_t)(o0 + ao) * CDIM + akq;

    // B cp.async mapping: 2 chunks of 16B per thread = full 16x128 tile
    const int br0 = t >> 5;                 // rows 0..7   (idx = t)
    const int bc0 = (t & 31) * 4;
    const int br1 = (256 + t) >> 5;         // rows 8..15  (idx = 256+t)
    const int bc1 = bc0;
    uint32_t bdst[2][2];
    bdst[0][0] = (uint32_t)__cvta_generic_to_shared(&Bs[0][br0][bc0]);
    bdst[0][1] = (uint32_t)__cvta_generic_to_shared(&Bs[0][br1][bc1]);
    bdst[1][0] = (uint32_t)__cvta_generic_to_shared(&Bs[1][br0][bc0]);
    bdst[1][1] = (uint32_t)__cvta_generic_to_shared(&Bs[1][br1][bc1]);
    const float* xp0 = Xb + (size_t)br0 * LDIM + l0 + bc0;
    const float* xp1 = Xb + (size_t)br1 * LDIM + l0 + bc1;

    // Prologue: B(0) cp.async, A(0) ldg
    cp16(bdst[0][0], xp0);
    cp16(bdst[0][1], xp1);
    cp_commit();
    float4 ra = *(const float4*)(wptr);

    uint64_t acc[4][4];
#pragma unroll
    for (int i = 0; i < 4; ++i)
#pragma unroll
        for (int j = 0; j < 4; ++j) acc[i][j] = 0ull;

    const int T = CDIM / 16;  // 16 k-steps
    for (int kt = 0; kt < T; ++kt) {
        const int st = kt & 1;
        // Store A(kt) dup'd (stage st last read at compute kt-2, fully synced)
        As[st][akq + 0][ao] = make_float2(ra.x, ra.x);
        As[st][akq + 1][ao] = make_float2(ra.y, ra.y);
        As[st][akq + 2][ao] = make_float2(ra.z, ra.z);
        As[st][akq + 3][ao] = make_float2(ra.w, ra.w);
        // Prefetch B(kt+1) into other stage (last read compute kt-1, synced)
        if (kt + 1 < T) {
            const size_t go = (size_t)(kt + 1) * 16 * LDIM;
            cp16(bdst[st ^ 1][0], xp0 + go);
            cp16(bdst[st ^ 1][1], xp1 + go);
        }
        cp_commit();
        cp_wait<1>();      // B(kt) resident
        __syncthreads();
        // A(kt+1) ldg, hidden under compute
        if (kt + 1 < T) ra = *(const float4*)(wptr + (kt + 1) * 16);

#pragma unroll
        for (int kk = 0; kk < 16; ++kk) {
            ulonglong2 aA = *(const ulonglong2*)&As[st][kk][4 * ty + 0];  // o0,o1 dup'd
            ulonglong2 aB = *(const ulonglong2*)&As[st][kk][4 * ty + 2];  // o2,o3 dup'd
            ulonglong2 b0 = *(const ulonglong2*)&Bs[st][kk][4 * tx];       // l pairs 0,1
            ulonglong2 b1 = *(const ulonglong2*)&Bs[st][kk][64 + 4 * tx];  // l pairs 2,3
            acc[0][0] = ffma2(aA.x, b0.x, acc[0][0]); acc[0][1] = ffma2(aA.x, b0.y, acc[0][1]);
            acc[0][2] = ffma2(aA.x, b1.x, acc[0][2]); acc[0][3] = ffma2(aA.x, b1.y, acc[0][3]);
            acc[1][0] = ffma2(aA.y, b0.x, acc[1][0]); acc[1][1] = ffma2(aA.y, b0.y, acc[1][1]);
            acc[1][2] = ffma2(aA.y, b1.x, acc[1][2]); acc[1][3] = ffma2(aA.y, b1.y, acc[1][3]);
            acc[2][0] = ffma2(aB.x, b0.x, acc[2][0]); acc[2][1] = ffma2(aB.x, b0.y, acc[2][1]);
            acc[2][2] = ffma2(aB.x, b1.x, acc[2][2]); acc[2][3] = ffma2(aB.x, b1.y, acc[2][3]);
            acc[3][0] = ffma2(aB.y, b0.x, acc[3][0]); acc[3][1] = ffma2(aB.y, b0.y, acc[3][1]);
            acc[3][2] = ffma2(aB.y, b1.x, acc[3][2]); acc[3][3] = ffma2(aB.y, b1.y, acc[3][3]);
        }
        __syncthreads();
    }

    // Epilogue: bias (+residual), float4 stores at l0+4tx and l0+64+4tx
#pragma unroll
    for (int oo = 0; oo < 4; ++oo) {
        const int o = o0 + 4 * ty + oo;
        const float bo = __ldg(&bias[o]);
        const size_t base = (size_t)b * M * LDIM + (size_t)o * LDIM;
#pragma unroll
        for (int half = 0; half < 2; ++half) {
            float2 v0 = unpack2(acc[oo][2 * half + 0]);
            float2 v1 = unpack2(acc[oo][2 * half + 1]);
            float4 v = make_float4(v0.x + bo, v0.y + bo, v1.x + bo, v1.y + bo);
            const size_t off = base + l0 + 64 * half + 4 * tx;
            if (RES) {
                float4 r = *(const float4*)&resid[off];
                v.x += r.x; v.y += r.y; v.z += r.z; v.w += r.w;
            }
            *(float4*)&out[off] = v;
        }
    }
}

// ---------------------------------------------------------------------------
// Attention: block = (b,h) x 64 queries, 1 query/thread (64-thread blocks for
// wave balance: grid 1024, ~6 CTAs/SM). f32x2 packed over ADJACENT KEYS,
// K/V natural [d][j] layout via cp.async double-buffer, broadcast LDS.128.
// 8 keys/iter -> 4 independent QK chains. Single-pass softmax.
// ---------------------------------------------------------------------------
__global__ __launch_bounds__(64, 6)
void attn_kernel(const float* __restrict__ qkv, float* __restrict__ attnout)
{
    __shared__ __align__(16) float Ks[2][32][64];  // [stage][d][j] 16KB
    __shared__ __align__(16) float Vs[2][32][64];  // 16KB

    const int bh  = blockIdx.x;
    const int b   = bh >> 3;
    const int h   = bh & 7;
    const int tid = threadIdx.x;                   // 0..63
    const int i   = blockIdx.y * 64 + tid;

    const float* Qp = qkv + (size_t)(b * 768 + h * 32) * LDIM;
    const float* Kp = qkv + (size_t)(b * 768 + 256 + h * 32) * LDIM;
    const float* Vp = qkv + (size_t)(b * 768 + 512 + h * 32) * LDIM;

    const float S = 0.17677669529663687f * 1.4426950408889634f;  // dh^-0.5 * log2e

    uint32_t ksm[2], vsm[2];
    ksm[0] = (uint32_t)__cvta_generic_to_shared(&Ks[0][0][0]);
    ksm[1] = (uint32_t)__cvta_generic_to_shared(&Ks[1][0][0]);
    vsm[0] = (uint32_t)__cvta_generic_to_shared(&Vs[0][0][0]);
    vsm[1] = (uint32_t)__cvta_generic_to_shared(&Vs[1][0][0]);

    uint64_t qd[32];
#pragma unroll
    for (int d = 0; d < 32; ++d)
        qd[d] = dup2(Qp[(size_t)d * LDIM + i] * S);

    uint64_t acc[32];
#pragma unroll
    for (int d = 0; d < 32; ++d) acc[d] = 0ull;
    float ls0 = 0.f, ls1 = 0.f;

    // tile copier: 8 K-chunks + 8 V-chunks (16B) per thread = full 32x64 tiles
    auto copy_tile = [&](int st, int j0) {
#pragma unroll
        for (int r = 0; r < 8; ++r) {
            const int idx = r * 64 + tid;        // 0..511
            const int row = idx >> 4;            // d 0..31
            const int ch  = (idx & 15) * 4;      // j-chunk
            const uint32_t soff = (uint32_t)(row * 64 + ch) * 4u;
            cp16(ksm[st] + soff, Kp + (size_t)row * LDIM + j0 + ch);
            cp16(vsm[st] + soff, Vp + (size_t)row * LDIM + j0 + ch);
        }
    };

    copy_tile(0, 0);
    cp_commit();

    for (int jt = 0; jt < 16; ++jt) {
        const int st = jt & 1;
        if (jt < 15) copy_tile(st ^ 1, (jt + 1) * 64);
        cp_commit();
        cp_wait<1>();
        __syncthreads();

#pragma unroll 1
        for (int jq = 0; jq < 8; ++jq) {          // 8 keys per iter
            uint64_t s0 = 0ull, s1 = 0ull, s2 = 0ull, s3 = 0ull;
#pragma unroll
            for (int d = 0; d < 32; ++d) {
                ulonglong2 k0 = *(const ulonglong2*)&Ks[st][d][8 * jq];
                ulonglong2 k1 = *(const ulonglong2*)&Ks[st][d][8 * jq + 4];
                s0 = ffma2(qd[d], k0.x, s0);
                s1 = ffma2(qd[d], k0.y, s1);
                s2 = ffma2(qd[d], k1.x, s2);
                s3 = ffma2(qd[d], k1.y, s3);
            }
            float2 f0 = unpack2(s0), f1 = unpack2(s1);
            float2 f2 = unpack2(s2), f3 = unpack2(s3);
            float p0 = ex2(f0.x), p1 = ex2(f0.y);
            float p2 = ex2(f1.x), p3 = ex2(f1.y);
            float p4 = ex2(f2.x), p5 = ex2(f2.y);
            float p6 = ex2(f3.x), p7 = ex2(f3.y);
            ls0 += (p0 + p1) + (p2 + p3);
            ls1 += (p4 + p5) + (p6 + p7);
            uint64_t pA = pack2(p0, p1), pB = pack2(p2, p3);
            uint64_t pC = pack2(p4, p5), pD = pack2(p6, p7);
#pragma unroll
            for (int d = 0; d < 32; ++d) {
                ulonglong2 v0 = *(const ulonglong2*)&Vs[st][d][8 * jq];
                ulonglong2 v1 = *(const ulonglong2*)&Vs[st][d][8 * jq + 4];
                uint64_t t0 = ffma2(pA, v0.x, acc[d]);
                uint64_t t1 = ffma2(pB, v0.y, t0);
                uint64_t t2 = ffma2(pC, v1.x, t1);
                acc[d] = ffma2(pD, v1.y, t2);
            }
        }
        __syncthreads();
    }

    const float inv = 1.f / (ls0 + ls1);
    float* Op = attnout + (size_t)(b * 256 + h * 32) * LDIM + i;
#pragma unroll
    for (int d = 0; d < 32; ++d) {
        float2 a = unpack2(acc[d]);
        Op[(size_t)d * LDIM] = (a.x + a.y) * inv;
    }
}

// ---------------------------------------------------------------------------
extern "C" void kernel_launch(void* const* d_in, const int* in_sizes, int n_in,
                              void* d_out, int out_size)
{
    const float* x      = (const float*)d_in[0];
    const float* w_qkv  = (const float*)d_in[1];
    const float* b_qkv  = (const float*)d_in[2];
    const float* w_proj = (const float*)d_in[3];
    const float* b_proj = (const float*)d_in[4];
    float* out = (float*)d_out;

    float *qkv = nullptr, *attn = nullptr;
    cudaGetSymbolAddress((void**)&qkv, g_qkv);
    cudaGetSymbolAddress((void**)&attn, g_attn);

    // QKV GEMM: M=768, tiles 64o x 128l
    gemm1x1<false><<<dim3(LDIM / 128, 768 / 64, BATCH), 256>>>(w_qkv, x, b_qkv, nullptr, qkv, 768);
    // Attention: 64 (b,h) x 16 query chunks of 64
    attn_kernel<<<dim3(64, 16), 64>>>(qkv, attn);
    // Proj + bias + residual: M=256
    gemm1x1<true><<<dim3(LDIM / 128, 256 / 64, BATCH), 256>>>(w_proj, attn, b_proj, x, out, 256);
}

// round 8
// speedup vs baseline: 1.2684x; 1.2684x over previous
#include <cuda_runtime.h>
#include <cstdint>

#define LDIM 1024   // h*w
#define CDIM 256
#define BATCH 8

// Scratch (no cudaMalloc allowed)
__device__ float g_qkv[BATCH * 3 * CDIM * LDIM];   // [b][768][l]
__device__ float g_attn[BATCH * LDIM * CDIM];      // [b][l][c]  (transposed)
__device__ float g_xt[BATCH * LDIM * CDIM];        // [b][l][c]  (transposed x)

// ---------- packed f32x2 helpers (attention) ----------
__device__ __forceinline__ uint64_t pack2(float x, float y) {
    uint64_t r; asm("mov.b64 %0, {%1, %2};" : "=l"(r) : "f"(x), "f"(y)); return r;
}
__device__ __forceinline__ uint64_t dup2(float x) {
    uint64_t r; asm("mov.b64 %0, {%1, %1};" : "=l"(r) : "f"(x)); return r;
}
__device__ __forceinline__ uint64_t ffma2(uint64_t a, uint64_t b, uint64_t c) {
    uint64_t d; asm("fma.rn.f32x2 %0, %1, %2, %3;" : "=l"(d) : "l"(a), "l"(b), "l"(c)); return d;
}
__device__ __forceinline__ float2 unpack2(uint64_t v) {
    float2 f; asm("mov.b64 {%0, %1}, %2;" : "=f"(f.x), "=f"(f.y) : "l"(v)); return f;
}
__device__ __forceinline__ float ex2(float x) {
    float r; asm("ex2.approx.f32 %0, %1;" : "=f"(r) : "f"(x)); return r;
}
__device__ __forceinline__ void cp16(uint32_t smem, const void* gmem) {
    asm volatile("cp.async.ca.shared.global [%0], [%1], 16;" :: "r"(smem), "l"(gmem));
}
__device__ __forceinline__ void cp_commit() { asm volatile("cp.async.commit_group;"); }
template<int N> __device__ __forceinline__ void cp_wait() {
    asm volatile("cp.async.wait_group %0;" :: "n"(N));
}
__device__ __forceinline__ uint32_t s2u(const void* p) {
    uint32_t a;
    asm("{ .reg .u64 t; cvta.to.shared.u64 t, %1; cvt.u32.u64 %0, t; }" : "=r"(a) : "l"(p));
    return a;
}

// ---------- mma.sync tf32 m16n8k8 (portable PTX, runs on tensor pipe) ----------
__device__ __forceinline__ void mma_tf32(float* d, const uint32_t* a, const uint32_t* b) {
    asm volatile(
        "mma.sync.aligned.m16n8k8.row.col.f32.tf32.tf32.f32 "
        "{%0,%1,%2,%3}, {%4,%5,%6,%7}, {%8,%9}, {%0,%1,%2,%3};"
        : "+f"(d[0]), "+f"(d[1]), "+f"(d[2]), "+f"(d[3])
        : "r"(a[0]), "r"(a[1]), "r"(a[2]), "r"(a[3]), "r"(b[0]), "r"(b[1]));
}

// ---------------------------------------------------------------------------
// Transpose: x[b][c][l] -> xt[b][l][c]
// ---------------------------------------------------------------------------
__global__ __launch_bounds__(256)
void transpose_cl(const float* __restrict__ x, float* __restrict__ xt)
{
    __shared__ float tile[32][33];
    const int b  = blockIdx.z;
    const int c0 = blockIdx.y * 32;
    const int l0 = blockIdx.x * 32;
    const int tx = threadIdx.x, ty = threadIdx.y;   // 32 x 8
    const float* xb  = x  + (size_t)b * CDIM * LDIM;
    float*       xtb = xt + (size_t)b * LDIM * CDIM;
#pragma unroll
    for (int r = 0; r < 32; r += 8)
        tile[ty + r][tx] = xb[(size_t)(c0 + ty + r) * LDIM + l0 + tx];
    __syncthreads();
#pragma unroll
    for (int r = 0; r < 32; r += 8)
        xtb[(size_t)(l0 + ty + r) * CDIM + c0 + tx] = tile[tx][ty + r];
}

// ---------------------------------------------------------------------------
// tf32 mma.sync GEMM: out[b][o][l] = sum_c W[o][c]*Bm[b][l][c] + bias[o] (+res)
// CTA 128(o) x 128(l), K=256 in 8 chunks of 32; 8 warps = 2(M) x 4(N),
// warp tile 64x32 = 4 m-frags x 4 n-frags of m16n8k8.
// smem [128][36] padded -> conflict-free fragment LDS. cp.async double-buffer.
// ---------------------------------------------------------------------------
#define APITCH 36
template<bool RES>
__global__ __launch_bounds__(256)
void gemm_mma(const float* __restrict__ W, const float* __restrict__ Bm,
              const float* __restrict__ bias, const float* __restrict__ resid,
              float* __restrict__ out, int M)
{
    extern __shared__ float sm[];
    float (*As)[128][APITCH] = (float(*)[128][APITCH])sm;                    // [2][128][36]
    float (*Bs)[128][APITCH] = (float(*)[128][APITCH])(sm + 2 * 128 * APITCH);

    const int b    = blockIdx.z;
    const int o0   = blockIdx.y * 128;
    const int l0   = blockIdx.x * 128;
    const int t    = threadIdx.x;
    const int wid  = t >> 5, lane = t & 31;
    const int wm   = (wid & 1) * 64;     // warp M offset
    const int wn   = (wid >> 1) * 32;    // warp N offset
    const int lr   = lane >> 2;          // 0..7
    const int lc   = lane & 3;           // 0..3

    const float* Wp = W  + (size_t)o0 * CDIM;
    const float* Bp = Bm + (size_t)b * LDIM * CDIM + (size_t)l0 * CDIM;

    const uint32_t asm_b = s2u(sm);
    const uint32_t bsm_b = asm_b + 2u * 128u * APITCH * 4u;

    // cp.async: per stage-load, 4 iters x (1 A + 1 B) 16B chunks per thread
    auto load_chunk = [&](int c, int st) {
        const uint32_t stoff = (uint32_t)st * 128u * APITCH * 4u;
#pragma unroll
        for (int r = 0; r < 4; ++r) {
            const int idx = r * 256 + t;          // 0..1023
            const int row = idx >> 3;             // 0..127
            const int c4  = (idx & 7) * 4;        // 0,4,...,28
            const uint32_t so = stoff + (uint32_t)(row * APITCH + c4) * 4u;
            cp16(asm_b + so, Wp + (size_t)row * CDIM + c * 32 + c4);
            cp16(bsm_b + so, Bp + (size_t)row * CDIM + c * 32 + c4);
        }
    };

    float acc[4][4][4];
#pragma unroll
    for (int i = 0; i < 4; ++i)
#pragma unroll
        for (int j = 0; j < 4; ++j)
#pragma unroll
            for (int k = 0; k < 4; ++k) acc[i][j][k] = 0.f;

    load_chunk(0, 0);
    cp_commit();

    for (int c = 0; c < 8; ++c) {
        if (c + 1 < 8) load_chunk(c + 1, (c + 1) & 1);
        cp_commit();
        cp_wait<1>();
        __syncthreads();
        const int st = c & 1;

#pragma unroll
        for (int ks = 0; ks < 4; ++ks) {
            const int kc = ks * 8 + lc;
            uint32_t af[4][4];
#pragma unroll
            for (int mf = 0; mf < 4; ++mf) {
                const int r0 = wm + mf * 16 + lr;
                af[mf][0] = __float_as_uint(As[st][r0][kc]);
                af[mf][1] = __float_as_uint(As[st][r0 + 8][kc]);
                af[mf][2] = __float_as_uint(As[st][r0][kc + 4]);
                af[mf][3] = __float_as_uint(As[st][r0 + 8][kc + 4]);
            }
            uint32_t bf[4][2];
#pragma unroll
            for (int nf = 0; nf < 4; ++nf) {
                const int n = wn + nf * 8 + lr;
                bf[nf][0] = __float_as_uint(Bs[st][n][kc]);
                bf[nf][1] = __float_as_uint(Bs[st][n][kc + 4]);
            }
#pragma unroll
            for (int mf = 0; mf < 4; ++mf)
#pragma unroll
                for (int nf = 0; nf < 4; ++nf)
                    mma_tf32(acc[mf][nf], af[mf], bf[nf]);
        }
        __syncthreads();
    }

    // Epilogue: c0/c1 at (row, 2*lc), c2/c3 at (row+8, 2*lc); float2 stores
#pragma unroll
    for (int mf = 0; mf < 4; ++mf) {
        const int r0 = o0 + wm + mf * 16 + lr;
        const float b0 = __ldg(&bias[r0]);
        const float b1 = __ldg(&bias[r0 + 8]);
        const size_t ro0 = ((size_t)b * M + r0) * LDIM;
        const size_t ro1 = ((size_t)b * M + r0 + 8) * LDIM;
#pragma unroll
        for (int nf = 0; nf < 4; ++nf) {
            const int cc = l0 + wn + nf * 8 + 2 * lc;
            float2 v0 = make_float2(acc[mf][nf][0] + b0, acc[mf][nf][1] + b0);
            float2 v1 = make_float2(acc[mf][nf][2] + b1, acc[mf][nf][3] + b1);
            if (RES) {
                float2 x0 = *(const float2*)&resid[ro0 + cc];
                float2 x1 = *(const float2*)&resid[ro1 + cc];
                v0.x += x0.x; v0.y += x0.y; v1.x += x1.x; v1.y += x1.y;
            }
            *(float2*)&out[ro0 + cc] = v0;
            *(float2*)&out[ro1 + cc] = v1;
        }
    }
}

// ---------------------------------------------------------------------------
// Attention (FFMA2): block = (b,h) x 64 queries, 1 query/thread.
// Writes output TRANSPOSED: g_attn[b][l][c] (contiguous 128B per thread).
// ---------------------------------------------------------------------------
__global__ __launch_bounds__(64, 6)
void attn_kernel(const float* __restrict__ qkv, float* __restrict__ attnout)
{
    __shared__ __align__(16) float Ks[2][32][64];
    __shared__ __align__(16) float Vs[2][32][64];

    const int bh  = blockIdx.x;
    const int b   = bh >> 3;
    const int h   = bh & 7;
    const int tid = threadIdx.x;                   // 0..63
    const int i   = blockIdx.y * 64 + tid;

    const float* Qp = qkv + (size_t)(b * 768 + h * 32) * LDIM;
    const float* Kp = qkv + (size_t)(b * 768 + 256 + h * 32) * LDIM;
    const float* Vp = qkv + (size_t)(b * 768 + 512 + h * 32) * LDIM;

    const float S = 0.17677669529663687f * 1.4426950408889634f;  // dh^-0.5 * log2e

    uint32_t ksm[2], vsm[2];
    ksm[0] = s2u(&Ks[0][0][0]); ksm[1] = s2u(&Ks[1][0][0]);
    vsm[0] = s2u(&Vs[0][0][0]); vsm[1] = s2u(&Vs[1][0][0]);

    uint64_t qd[32];
#pragma unroll
    for (int d = 0; d < 32; ++d)
        qd[d] = dup2(Qp[(size_t)d * LDIM + i] * S);

    uint64_t acc[32];
#pragma unroll
    for (int d = 0; d < 32; ++d) acc[d] = 0ull;
    float ls0 = 0.f, ls1 = 0.f;

    auto copy_tile = [&](int st, int j0) {
#pragma unroll
        for (int r = 0; r < 8; ++r) {
            const int idx = r * 64 + tid;
            const int row = idx >> 4;
            const int ch  = (idx & 15) * 4;
            const uint32_t soff = (uint32_t)(row * 64 + ch) * 4u;
            cp16(ksm[st] + soff, Kp + (size_t)row * LDIM + j0 + ch);
            cp16(vsm[st] + soff, Vp + (size_t)row * LDIM + j0 + ch);
        }
    };

    copy_tile(0, 0);
    cp_commit();

    for (int jt = 0; jt < 16; ++jt) {
        const int st = jt & 1;
        if (jt < 15) copy_tile(st ^ 1, (jt + 1) * 64);
        cp_commit();
        cp_wait<1>();
        __syncthreads();

#pragma unroll 1
        for (int jq = 0; jq < 8; ++jq) {
            uint64_t s0 = 0ull, s1 = 0ull, s2 = 0ull, s3 = 0ull;
#pragma unroll
            for (int d = 0; d < 32; ++d) {
                ulonglong2 k0 = *(const ulonglong2*)&Ks[st][d][8 * jq];
                ulonglong2 k1 = *(const ulonglong2*)&Ks[st][d][8 * jq + 4];
                s0 = ffma2(qd[d], k0.x, s0);
                s1 = ffma2(qd[d], k0.y, s1);
                s2 = ffma2(qd[d], k1.x, s2);
                s3 = ffma2(qd[d], k1.y, s3);
            }
            float2 f0 = unpack2(s0), f1 = unpack2(s1);
            float2 f2 = unpack2(s2), f3 = unpack2(s3);
            float p0 = ex2(f0.x), p1 = ex2(f0.y);
            float p2 = ex2(f1.x), p3 = ex2(f1.y);
            float p4 = ex2(f2.x), p5 = ex2(f2.y);
            float p6 = ex2(f3.x), p7 = ex2(f3.y);
            ls0 += (p0 + p1) + (p2 + p3);
            ls1 += (p4 + p5) + (p6 + p7);
            uint64_t pA = pack2(p0, p1), pB = pack2(p2, p3);
            uint64_t pC = pack2(p4, p5), pD = pack2(p6, p7);
#pragma unroll
            for (int d = 0; d < 32; ++d) {
                ulonglong2 v0 = *(const ulonglong2*)&Vs[st][d][8 * jq];
                ulonglong2 v1 = *(const ulonglong2*)&Vs[st][d][8 * jq + 4];
                uint64_t t0 = ffma2(pA, v0.x, acc[d]);
                uint64_t t1 = ffma2(pB, v0.y, t0);
                uint64_t t2 = ffma2(pC, v1.x, t1);
                acc[d] = ffma2(pD, v1.y, t2);
            }
        }
        __syncthreads();
    }

    const float inv = 1.f / (ls0 + ls1);
    float* Op = attnout + ((size_t)(b * LDIM + i)) * CDIM + h * 32;
#pragma unroll
    for (int dq = 0; dq < 8; ++dq) {
        float2 a0 = unpack2(acc[4 * dq + 0]);
        float2 a1 = unpack2(acc[4 * dq + 1]);
        float2 a2 = unpack2(acc[4 * dq + 2]);
        float2 a3 = unpack2(acc[4 * dq + 3]);
        float4 v = make_float4((a0.x + a0.y) * inv, (a1.x + a1.y) * inv,
                               (a2.x + a2.y) * inv, (a3.x + a3.y) * inv);
        *(float4*)(Op + 4 * dq) = v;
    }
}

// ---------------------------------------------------------------------------
extern "C" void kernel_launch(void* const* d_in, const int* in_sizes, int n_in,
                              void* d_out, int out_size)
{
    const float* x      = (const float*)d_in[0];
    const float* w_qkv  = (const float*)d_in[1];
    const float* b_qkv  = (const float*)d_in[2];
    const float* w_proj = (const float*)d_in[3];
    const float* b_proj = (const float*)d_in[4];
    float* out = (float*)d_out;

    float *qkv = nullptr, *attn = nullptr, *xt = nullptr;
    cudaGetSymbolAddress((void**)&qkv, g_qkv);
    cudaGetSymbolAddress((void**)&attn, g_attn);
    cudaGetSymbolAddress((void**)&xt, g_xt);

    const int SMEMSZ = 4 * 128 * APITCH * 4;   // 73728 bytes
    cudaFuncSetAttribute(gemm_mma<false>, cudaFuncAttributeMaxDynamicSharedMemorySize, SMEMSZ);
    cudaFuncSetAttribute(gemm_mma<true>,  cudaFuncAttributeMaxDynamicSharedMemorySize, SMEMSZ);

    // 1) transpose x -> xt[b][l][c]
    transpose_cl<<<dim3(LDIM / 32, CDIM / 32, BATCH), dim3(32, 8)>>>(x, xt);
    // 2) QKV GEMM (tf32 mma.sync): M=768
    gemm_mma<false><<<dim3(LDIM / 128, 768 / 128, BATCH), 256, SMEMSZ>>>(w_qkv, xt, b_qkv, nullptr, qkv, 768);
    // 3) attention (fp32 FFMA2), writes g_attn[b][l][c]
    attn_kernel<<<dim3(64, 16), 64>>>(qkv, attn);
    // 4) proj GEMM (tf32) + bias + residual: M=256
    gemm_mma<true><<<dim3(LDIM / 128, 256 / 128, BATCH), 256, SMEMSZ>>>(w_proj, attn, b_proj, x, out, 256);
}

// round 9
// speedup vs baseline: 1.9737x; 1.5560x over previous
#include <cuda_runtime.h>
#include <cstdint>

#define LDIM 1024   // h*w
#define CDIM 256
#define BATCH 8

// Scratch (no cudaMalloc allowed)
__device__ float g_qkv[BATCH * 3 * CDIM * LDIM];   // [b][768][l]
__device__ float g_attn[BATCH * LDIM * CDIM];      // [b][l][c]  (transposed)
__device__ float g_xt[BATCH * LDIM * CDIM];        // [b][l][c]  (transposed x)

// ---------- helpers ----------
__device__ __forceinline__ float ex2(float x) {
    float r; asm("ex2.approx.f32 %0, %1;" : "=f"(r) : "f"(x)); return r;
}
__device__ __forceinline__ void cp16(uint32_t smem, const void* gmem) {
    asm volatile("cp.async.ca.shared.global [%0], [%1], 16;" :: "r"(smem), "l"(gmem));
}
__device__ __forceinline__ void cp_commit() { asm volatile("cp.async.commit_group;"); }
template<int N> __device__ __forceinline__ void cp_wait() {
    asm volatile("cp.async.wait_group %0;" :: "n"(N));
}
__device__ __forceinline__ uint32_t s2u(const void* p) {
    uint32_t a;
    asm("{ .reg .u64 t; cvta.to.shared.u64 t, %1; cvt.u32.u64 %0, t; }" : "=r"(a) : "l"(p));
    return a;
}

// ---------- mma.sync tf32 m16n8k8 (portable PTX, tensor pipe) ----------
__device__ __forceinline__ void mma_tf32(float* d, const uint32_t* a, const uint32_t* b) {
    asm volatile(
        "mma.sync.aligned.m16n8k8.row.col.f32.tf32.tf32.f32 "
        "{%0,%1,%2,%3}, {%4,%5,%6,%7}, {%8,%9}, {%0,%1,%2,%3};"
        : "+f"(d[0]), "+f"(d[1]), "+f"(d[2]), "+f"(d[3])
        : "r"(a[0]), "r"(a[1]), "r"(a[2]), "r"(a[3]), "r"(b[0]), "r"(b[1]));
}

// ---------------------------------------------------------------------------
// Transpose: x[b][c][l] -> xt[b][l][c]
// ---------------------------------------------------------------------------
__global__ __launch_bounds__(256)
void transpose_cl(const float* __restrict__ x, float* __restrict__ xt)
{
    __shared__ float tile[32][33];
    const int b  = blockIdx.z;
    const int c0 = blockIdx.y * 32;
    const int l0 = blockIdx.x * 32;
    const int tx = threadIdx.x, ty = threadIdx.y;   // 32 x 8
    const float* xb  = x  + (size_t)b * CDIM * LDIM;
    float*       xtb = xt + (size_t)b * LDIM * CDIM;
#pragma unroll
    for (int r = 0; r < 32; r += 8)
        tile[ty + r][tx] = xb[(size_t)(c0 + ty + r) * LDIM + l0 + tx];
    __syncthreads();
#pragma unroll
    for (int r = 0; r < 32; r += 8)
        xtb[(size_t)(l0 + ty + r) * CDIM + c0 + tx] = tile[tx][ty + r];
}

// ---------------------------------------------------------------------------
// tf32 mma.sync GEMM: out[b][o][l] = sum_c W[o][c]*Bm[b][l][c] + bias[o] (+res)
// (unchanged from round 8 — validated)
// ---------------------------------------------------------------------------
#define APITCH 36
template<bool RES>
__global__ __launch_bounds__(256)
void gemm_mma(const float* __restrict__ W, const float* __restrict__ Bm,
              const float* __restrict__ bias, const float* __restrict__ resid,
              float* __restrict__ out, int M)
{
    extern __shared__ float sm[];
    float (*As)[128][APITCH] = (float(*)[128][APITCH])sm;
    float (*Bs)[128][APITCH] = (float(*)[128][APITCH])(sm + 2 * 128 * APITCH);

    const int b    = blockIdx.z;
    const int o0   = blockIdx.y * 128;
    const int l0   = blockIdx.x * 128;
    const int t    = threadIdx.x;
    const int wid  = t >> 5, lane = t & 31;
    const int wm   = (wid & 1) * 64;
    const int wn   = (wid >> 1) * 32;
    const int lr   = lane >> 2;
    const int lc   = lane & 3;

    const float* Wp = W  + (size_t)o0 * CDIM;
    const float* Bp = Bm + (size_t)b * LDIM * CDIM + (size_t)l0 * CDIM;

    const uint32_t asm_b = s2u(sm);
    const uint32_t bsm_b = asm_b + 2u * 128u * APITCH * 4u;

    auto load_chunk = [&](int c, int st) {
        const uint32_t stoff = (uint32_t)st * 128u * APITCH * 4u;
#pragma unroll
        for (int r = 0; r < 4; ++r) {
            const int idx = r * 256 + t;
            const int row = idx >> 3;
            const int c4  = (idx & 7) * 4;
            const uint32_t so = stoff + (uint32_t)(row * APITCH + c4) * 4u;
            cp16(asm_b + so, Wp + (size_t)row * CDIM + c * 32 + c4);
            cp16(bsm_b + so, Bp + (size_t)row * CDIM + c * 32 + c4);
        }
    };

    float acc[4][4][4];
#pragma unroll
    for (int i = 0; i < 4; ++i)
#pragma unroll
        for (int j = 0; j < 4; ++j)
#pragma unroll
            for (int k = 0; k < 4; ++k) acc[i][j][k] = 0.f;

    load_chunk(0, 0);
    cp_commit();

    for (int c = 0; c < 8; ++c) {
        if (c + 1 < 8) load_chunk(c + 1, (c + 1) & 1);
        cp_commit();
        cp_wait<1>();
        __syncthreads();
        const int st = c & 1;

#pragma unroll
        for (int ks = 0; ks < 4; ++ks) {
            const int kc = ks * 8 + lc;
            uint32_t af[4][4];
#pragma unroll
            for (int mf = 0; mf < 4; ++mf) {
                const int r0 = wm + mf * 16 + lr;
                af[mf][0] = __float_as_uint(As[st][r0][kc]);
                af[mf][1] = __float_as_uint(As[st][r0 + 8][kc]);
                af[mf][2] = __float_as_uint(As[st][r0][kc + 4]);
                af[mf][3] = __float_as_uint(As[st][r0 + 8][kc + 4]);
            }
            uint32_t bf[4][2];
#pragma unroll
            for (int nf = 0; nf < 4; ++nf) {
                const int n = wn + nf * 8 + lr;
                bf[nf][0] = __float_as_uint(Bs[st][n][kc]);
                bf[nf][1] = __float_as_uint(Bs[st][n][kc + 4]);
            }
#pragma unroll
            for (int mf = 0; mf < 4; ++mf)
#pragma unroll
                for (int nf = 0; nf < 4; ++nf)
                    mma_tf32(acc[mf][nf], af[mf], bf[nf]);
        }
        __syncthreads();
    }

#pragma unroll
    for (int mf = 0; mf < 4; ++mf) {
        const int r0 = o0 + wm + mf * 16 + lr;
        const float b0 = __ldg(&bias[r0]);
        const float b1 = __ldg(&bias[r0 + 8]);
        const size_t ro0 = ((size_t)b * M + r0) * LDIM;
        const size_t ro1 = ((size_t)b * M + r0 + 8) * LDIM;
#pragma unroll
        for (int nf = 0; nf < 4; ++nf) {
            const int cc = l0 + wn + nf * 8 + 2 * lc;
            float2 v0 = make_float2(acc[mf][nf][0] + b0, acc[mf][nf][1] + b0);
            float2 v1 = make_float2(acc[mf][nf][2] + b1, acc[mf][nf][3] + b1);
            if (RES) {
                float2 x0 = *(const float2*)&resid[ro0 + cc];
                float2 x1 = *(const float2*)&resid[ro1 + cc];
                v0.x += x0.x; v0.y += x0.y; v1.x += x1.x; v1.y += x1.y;
            }
            *(float2*)&out[ro0 + cc] = v0;
            *(float2*)&out[ro1 + cc] = v1;
        }
    }
}

// ---------------------------------------------------------------------------
// Flash attention on tf32 mma.sync.
// CTA = one (b,h) x 64 queries; 4 warps x 16 query rows.
// qkv layout [d][l]: K tile [d][j] (pitch 72) and V tile [d][j] (pitch 68)
// copied natively (cp.async, double-buffered); Q gathered once to fragments.
// P (exp2'd probs) round-trips per-warp smem (pitch 68). All fragment LDS
// conflict-free by pitch construction. Single-pass softmax, quad-shuffle
// row sums, normalize at end. Output written [b][l][c] for the proj GEMM.
// ---------------------------------------------------------------------------
#define KPITCH 72
#define VPITCH 68
#define PPITCH 68
// floats: 2*32*72=4608 (K stages) + 2*32*68=4352 (V stages) + 4*16*68=4352 (P)
#define ATTN_SMEM_FLOATS (4608 + 4352 + 4352)

__global__ __launch_bounds__(128)
void attn_mma(const float* __restrict__ qkv, float* __restrict__ attnout)
{
    extern __shared__ float smf[];
    const int bh   = blockIdx.x;
    const int b    = bh >> 3;
    const int h    = bh & 7;
    const int qt   = blockIdx.y;
    const int t    = threadIdx.x;
    const int wid  = t >> 5, lane = t & 31;
    const int lr   = lane >> 2;   // 0..7
    const int lc   = lane & 3;    // 0..3

    float* KS[2] = { smf,        smf + 32 * KPITCH };
    float* VS[2] = { smf + 4608, smf + 4608 + 32 * VPITCH };
    float* PS    = smf + 4608 + 4352 + wid * 16 * PPITCH;

    const float* Qp = qkv + (size_t)(b * 768 + h * 32) * LDIM;
    const float* Kp = qkv + (size_t)(b * 768 + 256 + h * 32) * LDIM;
    const float* Vp = qkv + (size_t)(b * 768 + 512 + h * 32) * LDIM;

    const float S = 0.17677669529663687f * 1.4426950408889634f;  // dh^-0.5 * log2e

    const int i0 = qt * 64 + wid * 16;

    // Q fragments (once): a-frag (row, d) mapping of m16n8k8
    uint32_t qf[4][4];
#pragma unroll
    for (int ks = 0; ks < 4; ++ks) {
        const int d0 = 8 * ks + lc;
        qf[ks][0] = __float_as_uint(Qp[(size_t)d0 * LDIM + i0 + lr] * S);
        qf[ks][1] = __float_as_uint(Qp[(size_t)d0 * LDIM + i0 + lr + 8] * S);
        qf[ks][2] = __float_as_uint(Qp[(size_t)(d0 + 4) * LDIM + i0 + lr] * S);
        qf[ks][3] = __float_as_uint(Qp[(size_t)(d0 + 4) * LDIM + i0 + lr + 8] * S);
    }

    float o[4][4];
#pragma unroll
    for (int i = 0; i < 4; ++i)
#pragma unroll
        for (int j = 0; j < 4; ++j) o[i][j] = 0.f;
    float rs0 = 0.f, rs1 = 0.f;

    const uint32_t ks_u[2] = { s2u(KS[0]), s2u(KS[1]) };
    const uint32_t vs_u[2] = { s2u(VS[0]), s2u(VS[1]) };

    auto copy_tile = [&](int st, int j0) {
#pragma unroll
        for (int r = 0; r < 4; ++r) {
            const int idx = r * 128 + t;          // 0..511
            const int d   = idx >> 4;             // 0..31
            const int jc  = (idx & 15) * 4;       // 0..60
            cp16(ks_u[st] + (uint32_t)(d * KPITCH + jc) * 4u, Kp + (size_t)d * LDIM + j0 + jc);
            cp16(vs_u[st] + (uint32_t)(d * VPITCH + jc) * 4u, Vp + (size_t)d * LDIM + j0 + jc);
        }
    };

    copy_tile(0, 0);
    cp_commit();

    for (int jt = 0; jt < 16; ++jt) {
        const int st = jt & 1;
        if (jt < 15) copy_tile(st ^ 1, (jt + 1) * 64);
        cp_commit();
        cp_wait<1>();
        __syncthreads();

        // ---- QK: P[16][64] per warp ----
        float c[8][4];
#pragma unroll
        for (int nf = 0; nf < 8; ++nf)
#pragma unroll
            for (int k = 0; k < 4; ++k) c[nf][k] = 0.f;

#pragma unroll
        for (int ks = 0; ks < 4; ++ks) {
            uint32_t bf[8][2];
#pragma unroll
            for (int nf = 0; nf < 8; ++nf) {
                bf[nf][0] = __float_as_uint(KS[st][(8 * ks + lc) * KPITCH + 8 * nf + lr]);
                bf[nf][1] = __float_as_uint(KS[st][(8 * ks + 4 + lc) * KPITCH + 8 * nf + lr]);
            }
#pragma unroll
            for (int nf = 0; nf < 8; ++nf)
                mma_tf32(c[nf], qf[ks], bf[nf]);
        }

        // ---- exp2 + row sums + stage P to per-warp smem ----
#pragma unroll
        for (int nf = 0; nf < 8; ++nf) {
            const float p0 = ex2(c[nf][0]), p1 = ex2(c[nf][1]);
            const float p2 = ex2(c[nf][2]), p3 = ex2(c[nf][3]);
            rs0 += p0 + p1;
            rs1 += p2 + p3;
            *(float2*)&PS[lr * PPITCH + 8 * nf + 2 * lc]       = make_float2(p0, p1);
            *(float2*)&PS[(lr + 8) * PPITCH + 8 * nf + 2 * lc] = make_float2(p2, p3);
        }
        __syncwarp();

        // ---- PV: O[16][32] += P[16][64] * V[64][32] ----
#pragma unroll
        for (int ks2 = 0; ks2 < 8; ++ks2) {
            uint32_t af[4];
            af[0] = __float_as_uint(PS[lr * PPITCH + 8 * ks2 + lc]);
            af[1] = __float_as_uint(PS[(lr + 8) * PPITCH + 8 * ks2 + lc]);
            af[2] = __float_as_uint(PS[lr * PPITCH + 8 * ks2 + 4 + lc]);
            af[3] = __float_as_uint(PS[(lr + 8) * PPITCH + 8 * ks2 + 4 + lc]);
#pragma unroll
            for (int nf2 = 0; nf2 < 4; ++nf2) {
                uint32_t bf2[2];
                bf2[0] = __float_as_uint(VS[st][(8 * nf2 + lr) * VPITCH + 8 * ks2 + lc]);
                bf2[1] = __float_as_uint(VS[st][(8 * nf2 + lr) * VPITCH + 8 * ks2 + 4 + lc]);
                mma_tf32(o[nf2], af, bf2);
            }
        }
        __syncthreads();
    }

    // quad reduce row sums (lanes sharing lane>>2)
    rs0 += __shfl_xor_sync(0xFFFFFFFFu, rs0, 1);
    rs0 += __shfl_xor_sync(0xFFFFFFFFu, rs0, 2);
    rs1 += __shfl_xor_sync(0xFFFFFFFFu, rs1, 1);
    rs1 += __shfl_xor_sync(0xFFFFFFFFu, rs1, 2);
    const float inv0 = 1.f / rs0;
    const float inv1 = 1.f / rs1;

    // write O -> attnout[b][l][c]
#pragma unroll
    for (int nf2 = 0; nf2 < 4; ++nf2) {
        const int col = h * 32 + 8 * nf2 + 2 * lc;
        const size_t r0 = ((size_t)b * LDIM + i0 + lr) * CDIM + col;
        const size_t r1 = ((size_t)b * LDIM + i0 + lr + 8) * CDIM + col;
        *(float2*)&attnout[r0] = make_float2(o[nf2][0] * inv0, o[nf2][1] * inv0);
        *(float2*)&attnout[r1] = make_float2(o[nf2][2] * inv1, o[nf2][3] * inv1);
    }
}

// ---------------------------------------------------------------------------
extern "C" void kernel_launch(void* const* d_in, const int* in_sizes, int n_in,
                              void* d_out, int out_size)
{
    const float* x      = (const float*)d_in[0];
    const float* w_qkv  = (const float*)d_in[1];
    const float* b_qkv  = (const float*)d_in[2];
    const float* w_proj = (const float*)d_in[3];
    const float* b_proj = (const float*)d_in[4];
    float* out = (float*)d_out;

    float *qkv = nullptr, *attn = nullptr, *xt = nullptr;
    cudaGetSymbolAddress((void**)&qkv, g_qkv);
    cudaGetSymbolAddress((void**)&attn, g_attn);
    cudaGetSymbolAddress((void**)&xt, g_xt);

    const int SMEMSZ  = 4 * 128 * APITCH * 4;              // 73728 B (gemm)
    const int ASMEMSZ = ATTN_SMEM_FLOATS * 4;              // 53248 B (attention)
    cudaFuncSetAttribute(gemm_mma<false>, cudaFuncAttributeMaxDynamicSharedMemorySize, SMEMSZ);
    cudaFuncSetAttribute(gemm_mma<true>,  cudaFuncAttributeMaxDynamicSharedMemorySize, SMEMSZ);
    cudaFuncSetAttribute(attn_mma, cudaFuncAttributeMaxDynamicSharedMemorySize, ASMEMSZ);

    // 1) transpose x -> xt[b][l][c]
    transpose_cl<<<dim3(LDIM / 32, CDIM / 32, BATCH), dim3(32, 8)>>>(x, xt);
    // 2) QKV GEMM (tf32 mma.sync): M=768, out [b][768][l]
    gemm_mma<false><<<dim3(LDIM / 128, 768 / 128, BATCH), 256, SMEMSZ>>>(w_qkv, xt, b_qkv, nullptr, qkv, 768);
    // 3) flash attention (tf32 mma.sync), writes g_attn[b][l][c]
    attn_mma<<<dim3(64, LDIM / 64), 128, ASMEMSZ>>>(qkv, attn);
    // 4) proj GEMM (tf32) + bias + residual: M=256
    gemm_mma<true><<<dim3(LDIM / 128, 256 / 128, BATCH), 256, SMEMSZ>>>(w_proj, attn, b_proj, x, out, 256);
}

// round 10
// speedup vs baseline: 3.4742x; 1.7603x over previous
#include <cuda_runtime.h>
#include <cstdint>

#define LDIM 1024   // h*w
#define CDIM 256
#define BATCH 8

// Scratch (no cudaMalloc allowed)
__device__ float g_qkv[BATCH * 3 * CDIM * LDIM];   // [b][768][l]
__device__ float g_attn[BATCH * LDIM * CDIM];      // [b][l][c]  (transposed)
__device__ float g_xt[BATCH * LDIM * CDIM];        // [b][l][c]  (transposed x)
__device__ float g_kt[BATCH * 8 * LDIM * 32];      // [bh][j][d] (K transposed)

// ---------- helpers ----------
__device__ __forceinline__ float ex2(float x) {
    float r; asm("ex2.approx.f32 %0, %1;" : "=f"(r) : "f"(x)); return r;
}
__device__ __forceinline__ void cp16(uint32_t smem, const void* gmem) {
    asm volatile("cp.async.ca.shared.global [%0], [%1], 16;" :: "r"(smem), "l"(gmem));
}
__device__ __forceinline__ void cp_commit() { asm volatile("cp.async.commit_group;"); }
template<int N> __device__ __forceinline__ void cp_wait() {
    asm volatile("cp.async.wait_group %0;" :: "n"(N));
}
__device__ __forceinline__ uint32_t s2u(const void* p) {
    uint32_t a;
    asm("{ .reg .u64 t; cvta.to.shared.u64 t, %1; cvt.u32.u64 %0, t; }" : "=r"(a) : "l"(p));
    return a;
}
// ldmatrix x4: four 8x8 b16 matrices == four 8x4 f32 tiles (one f32 per lane each)
__device__ __forceinline__ void ldsm4(uint32_t& r0, uint32_t& r1, uint32_t& r2, uint32_t& r3,
                                      uint32_t addr) {
    asm volatile("ldmatrix.sync.aligned.m8n8.x4.shared.b16 {%0,%1,%2,%3}, [%4];"
                 : "=r"(r0), "=r"(r1), "=r"(r2), "=r"(r3) : "r"(addr));
}

// ---------- mma.sync tf32 m16n8k8 ----------
__device__ __forceinline__ void mma_tf32(float* d, const uint32_t* a, const uint32_t* b) {
    asm volatile(
        "mma.sync.aligned.m16n8k8.row.col.f32.tf32.tf32.f32 "
        "{%0,%1,%2,%3}, {%4,%5,%6,%7}, {%8,%9}, {%0,%1,%2,%3};"
        : "+f"(d[0]), "+f"(d[1]), "+f"(d[2]), "+f"(d[3])
        : "r"(a[0]), "r"(a[1]), "r"(a[2]), "r"(a[3]), "r"(b[0]), "r"(b[1]));
}

// ---------------------------------------------------------------------------
// Transpose: x[b][c][l] -> xt[b][l][c]
// ---------------------------------------------------------------------------
__global__ __launch_bounds__(256)
void transpose_cl(const float* __restrict__ x, float* __restrict__ xt)
{
    __shared__ float tile[32][33];
    const int b  = blockIdx.z;
    const int c0 = blockIdx.y * 32;
    const int l0 = blockIdx.x * 32;
    const int tx = threadIdx.x, ty = threadIdx.y;   // 32 x 8
    const float* xb  = x  + (size_t)b * CDIM * LDIM;
    float*       xtb = xt + (size_t)b * LDIM * CDIM;
#pragma unroll
    for (int r = 0; r < 32; r += 8)
        tile[ty + r][tx] = xb[(size_t)(c0 + ty + r) * LDIM + l0 + tx];
    __syncthreads();
#pragma unroll
    for (int r = 0; r < 32; r += 8)
        xtb[(size_t)(l0 + ty + r) * CDIM + c0 + tx] = tile[tx][ty + r];
}

// ---------------------------------------------------------------------------
// K transpose: qkv K slice [d=32][l=1024] per (b,h) -> kt[bh][j=1024][d=32]
// ---------------------------------------------------------------------------
__global__ __launch_bounds__(256)
void transpose_k(const float* __restrict__ qkv, float* __restrict__ kt)
{
    __shared__ float tile[32][33];
    const int bh = blockIdx.y;
    const int b  = bh >> 3, h = bh & 7;
    const int l0 = blockIdx.x * 32;
    const int tx = threadIdx.x, ty = threadIdx.y;   // 32 x 8
    const float* Kp  = qkv + (size_t)(b * 768 + 256 + h * 32) * LDIM;
    float*       out = kt + (size_t)bh * LDIM * 32 + (size_t)l0 * 32;
#pragma unroll
    for (int r = 0; r < 32; r += 8)
        tile[ty + r][tx] = Kp[(size_t)(ty + r) * LDIM + l0 + tx];
    __syncthreads();
#pragma unroll
    for (int r = 0; r < 32; r += 8)
        out[(size_t)(ty + r) * 32 + tx] = tile[tx][ty + r];
}

// ---------------------------------------------------------------------------
// tf32 mma.sync GEMM (unchanged from round 8/9 — validated)
// ---------------------------------------------------------------------------
#define APITCH 36
template<bool RES>
__global__ __launch_bounds__(256)
void gemm_mma(const float* __restrict__ W, const float* __restrict__ Bm,
              const float* __restrict__ bias, const float* __restrict__ resid,
              float* __restrict__ out, int M)
{
    extern __shared__ float sm[];
    float (*As)[128][APITCH] = (float(*)[128][APITCH])sm;
    float (*Bs)[128][APITCH] = (float(*)[128][APITCH])(sm + 2 * 128 * APITCH);

    const int b    = blockIdx.z;
    const int o0   = blockIdx.y * 128;
    const int l0   = blockIdx.x * 128;
    const int t    = threadIdx.x;
    const int wid  = t >> 5, lane = t & 31;
    const int wm   = (wid & 1) * 64;
    const int wn   = (wid >> 1) * 32;
    const int lr   = lane >> 2;
    const int lc   = lane & 3;

    const float* Wp = W  + (size_t)o0 * CDIM;
    const float* Bp = Bm + (size_t)b * LDIM * CDIM + (size_t)l0 * CDIM;

    const uint32_t asm_b = s2u(sm);
    const uint32_t bsm_b = asm_b + 2u * 128u * APITCH * 4u;

    auto load_chunk = [&](int c, int st) {
        const uint32_t stoff = (uint32_t)st * 128u * APITCH * 4u;
#pragma unroll
        for (int r = 0; r < 4; ++r) {
            const int idx = r * 256 + t;
            const int row = idx >> 3;
            const int c4  = (idx & 7) * 4;
            const uint32_t so = stoff + (uint32_t)(row * APITCH + c4) * 4u;
            cp16(asm_b + so, Wp + (size_t)row * CDIM + c * 32 + c4);
            cp16(bsm_b + so, Bp + (size_t)row * CDIM + c * 32 + c4);
        }
    };

    float acc[4][4][4];
#pragma unroll
    for (int i = 0; i < 4; ++i)
#pragma unroll
        for (int j = 0; j < 4; ++j)
#pragma unroll
            for (int k = 0; k < 4; ++k) acc[i][j][k] = 0.f;

    load_chunk(0, 0);
    cp_commit();

    for (int c = 0; c < 8; ++c) {
        if (c + 1 < 8) load_chunk(c + 1, (c + 1) & 1);
        cp_commit();
        cp_wait<1>();
        __syncthreads();
        const int st = c & 1;

#pragma unroll
        for (int ks = 0; ks < 4; ++ks) {
            const int kc = ks * 8 + lc;
            uint32_t af[4][4];
#pragma unroll
            for (int mf = 0; mf < 4; ++mf) {
                const int r0 = wm + mf * 16 + lr;
                af[mf][0] = __float_as_uint(As[st][r0][kc]);
                af[mf][1] = __float_as_uint(As[st][r0 + 8][kc]);
                af[mf][2] = __float_as_uint(As[st][r0][kc + 4]);
                af[mf][3] = __float_as_uint(As[st][r0 + 8][kc + 4]);
            }
            uint32_t bf[4][2];
#pragma unroll
            for (int nf = 0; nf < 4; ++nf) {
                const int n = wn + nf * 8 + lr;
                bf[nf][0] = __float_as_uint(Bs[st][n][kc]);
                bf[nf][1] = __float_as_uint(Bs[st][n][kc + 4]);
            }
#pragma unroll
            for (int mf = 0; mf < 4; ++mf)
#pragma unroll
                for (int nf = 0; nf < 4; ++nf)
                    mma_tf32(acc[mf][nf], af[mf], bf[nf]);
        }
        __syncthreads();
    }

#pragma unroll
    for (int mf = 0; mf < 4; ++mf) {
        const int r0 = o0 + wm + mf * 16 + lr;
        const float b0 = __ldg(&bias[r0]);
        const float b1 = __ldg(&bias[r0 + 8]);
        const size_t ro0 = ((size_t)b * M + r0) * LDIM;
        const size_t ro1 = ((size_t)b * M + r0 + 8) * LDIM;
#pragma unroll
        for (int nf = 0; nf < 4; ++nf) {
            const int cc = l0 + wn + nf * 8 + 2 * lc;
            float2 v0 = make_float2(acc[mf][nf][0] + b0, acc[mf][nf][1] + b0);
            float2 v1 = make_float2(acc[mf][nf][2] + b1, acc[mf][nf][3] + b1);
            if (RES) {
                float2 x0 = *(const float2*)&resid[ro0 + cc];
                float2 x1 = *(const float2*)&resid[ro1 + cc];
                v0.x += x0.x; v0.y += x0.y; v1.x += x1.x; v1.y += x1.y;
            }
            *(float2*)&out[ro0 + cc] = v0;
            *(float2*)&out[ro1 + cc] = v1;
        }
    }
}

// ---------------------------------------------------------------------------
// Flash attention, tf32 mma.sync + ldmatrix fragment loads.
// CTA = one (b,h) x 64 queries; 4 warps x 16 rows. K from kt[bh][j][d]
// (ldmatrix-native for QK B-frags), V from qkv [d][j] (native for PV B-frags),
// P round-trips per-warp smem read back via ldmatrix A-frags.
// Pitches 36/68/68: pitch/4 ≡ 1 mod 8 -> conflict-free ldmatrix.
// ---------------------------------------------------------------------------
#define KTP 36   // kt tile pitch (floats), rows j
#define VTP 68   // v tile pitch, rows d
#define PTP 68   // p tile pitch, rows i
// floats: K 2*64*36=4608, V 2*32*68=4352, P 4*16*68=4352
#define ATTN_SMEM_FLOATS (4608 + 4352 + 4352)

__global__ __launch_bounds__(128)
void attn_mma(const float* __restrict__ qkv, const float* __restrict__ kt,
              float* __restrict__ attnout)
{
    extern __shared__ float smf[];
    const int bh   = blockIdx.x;
    const int b    = bh >> 3;
    const int h    = bh & 7;
    const int qt   = blockIdx.y;
    const int t    = threadIdx.x;
    const int wid  = t >> 5, lane = t & 31;
    const int lr   = lane >> 2;   // 0..7
    const int lc   = lane & 3;    // 0..3

    float* KS[2] = { smf,        smf + 64 * KTP };
    float* VS[2] = { smf + 4608, smf + 4608 + 32 * VTP };
    float* PS    = smf + 4608 + 4352 + wid * 16 * PTP;

    const float* Qp  = qkv + (size_t)(b * 768 + h * 32) * LDIM;
    const float* Vp  = qkv + (size_t)(b * 768 + 512 + h * 32) * LDIM;
    const float* Ktp = kt + (size_t)bh * LDIM * 32;

    const float S = 0.17677669529663687f * 1.4426950408889634f;  // dh^-0.5 * log2e

    const int i0 = qt * 64 + wid * 16;

    // Q fragments (once)
    uint32_t qf[4][4];
#pragma unroll
    for (int ks = 0; ks < 4; ++ks) {
        const int d0 = 8 * ks + lc;
        qf[ks][0] = __float_as_uint(Qp[(size_t)d0 * LDIM + i0 + lr] * S);
        qf[ks][1] = __float_as_uint(Qp[(size_t)d0 * LDIM + i0 + lr + 8] * S);
        qf[ks][2] = __float_as_uint(Qp[(size_t)(d0 + 4) * LDIM + i0 + lr] * S);
        qf[ks][3] = __float_as_uint(Qp[(size_t)(d0 + 4) * LDIM + i0 + lr + 8] * S);
    }

    float o[4][4];
#pragma unroll
    for (int i = 0; i < 4; ++i)
#pragma unroll
        for (int j = 0; j < 4; ++j) o[i][j] = 0.f;
    float rs0 = 0.f, rs1 = 0.f;

    const uint32_t ks_u[2] = { s2u(KS[0]), s2u(KS[1]) };
    const uint32_t vs_u[2] = { s2u(VS[0]), s2u(VS[1]) };
    const uint32_t ps_u    = s2u(PS);

    // ---- per-lane ldmatrix address components ----
    const int mi = lane >> 3;            // matrix index 0..3
    const int mr = lane & 7;             // row within matrix
    // QK bf (K tile [j][d]): matrices (j-half, d-half)
    const uint32_t qk_lm = (uint32_t)(((mi >> 1) * 8 + mr) * KTP + (mi & 1) * 4) * 4u;
    // PV A (P tile [i][j]): m0 rows0-7, m1 rows8-15, m2 +4col, m3 rows8-15 +4col
    const uint32_t pa_lm = ps_u + (uint32_t)(((mi & 1) * 8 + mr) * PTP + (mi >> 1) * 4) * 4u;
    // PV bf2 (V tile [d][j]): all matrices same rows, cols 0,4,8,12
    const uint32_t pv_lm = (uint32_t)(mr * VTP + mi * 4) * 4u;

    auto copy_tile = [&](int st, int j0) {
        // K: 64 rows x 32 floats, contiguous in kt
#pragma unroll
        for (int r = 0; r < 4; ++r) {
            const int idx = r * 128 + t;              // 0..511
            const int j   = idx >> 3;                 // 0..63
            const int ch  = (idx & 7) * 4;            // 0..28
            cp16(ks_u[st] + (uint32_t)(j * KTP + ch) * 4u,
                 Ktp + (size_t)(j0 + j) * 32 + ch);
        }
        // V: 32 rows x 64 floats from [d][l]
#pragma unroll
        for (int r = 0; r < 4; ++r) {
            const int idx = r * 128 + t;              // 0..511
            const int d   = idx >> 4;                 // 0..31
            const int jc  = (idx & 15) * 4;           // 0..60
            cp16(vs_u[st] + (uint32_t)(d * VTP + jc) * 4u,
                 Vp + (size_t)d * LDIM + j0 + jc);
        }
    };

    copy_tile(0, 0);
    cp_commit();

    for (int jt = 0; jt < 16; ++jt) {
        const int st = jt & 1;
        if (jt < 15) copy_tile(st ^ 1, (jt + 1) * 64);
        cp_commit();
        cp_wait<1>();
        __syncthreads();

        // ---- QK: S[16][64] per warp ----
        float c[8][4];
#pragma unroll
        for (int nf = 0; nf < 8; ++nf)
#pragma unroll
            for (int k = 0; k < 4; ++k) c[nf][k] = 0.f;

#pragma unroll
        for (int ks = 0; ks < 4; ++ks) {
#pragma unroll
            for (int nfp = 0; nfp < 4; ++nfp) {   // nf = 2nfp, 2nfp+1
                uint32_t b0, b1, b2, b3;
                ldsm4(b0, b1, b2, b3,
                      ks_u[st] + qk_lm + (uint32_t)(nfp * 16 * KTP + ks * 8) * 4u);
                uint32_t bfA[2] = { b0, b1 }, bfB[2] = { b2, b3 };
                mma_tf32(c[2 * nfp],     qf[ks], bfA);
                mma_tf32(c[2 * nfp + 1], qf[ks], bfB);
            }
        }

        // ---- exp2 + row sums + stage P ----
#pragma unroll
        for (int nf = 0; nf < 8; ++nf) {
            const float p0 = ex2(c[nf][0]), p1 = ex2(c[nf][1]);
            const float p2 = ex2(c[nf][2]), p3 = ex2(c[nf][3]);
            rs0 += p0 + p1;
            rs1 += p2 + p3;
            *(float2*)&PS[lr * PTP + 8 * nf + 2 * lc]       = make_float2(p0, p1);
            *(float2*)&PS[(lr + 8) * PTP + 8 * nf + 2 * lc] = make_float2(p2, p3);
        }
        __syncwarp();

        // ---- PV: O[16][32] += P[16][64] * V[64][32] ----
#pragma unroll
        for (int kp = 0; kp < 4; ++kp) {          // ks2 = 2kp, 2kp+1
            uint32_t aA[4], aB[4];
            ldsm4(aA[0], aA[1], aA[2], aA[3], pa_lm + (uint32_t)(2 * kp * 8) * 4u);
            ldsm4(aB[0], aB[1], aB[2], aB[3], pa_lm + (uint32_t)((2 * kp + 1) * 8) * 4u);
#pragma unroll
            for (int nf2 = 0; nf2 < 4; ++nf2) {
                uint32_t v0, v1, v2, v3;
                ldsm4(v0, v1, v2, v3,
                      vs_u[st] + pv_lm + (uint32_t)(nf2 * 8 * VTP + kp * 16) * 4u);
                uint32_t bfA[2] = { v0, v1 }, bfB[2] = { v2, v3 };
                mma_tf32(o[nf2], aA, bfA);
                mma_tf32(o[nf2], aB, bfB);
            }
        }
        __syncthreads();
    }

    // quad reduce row sums
    rs0 += __shfl_xor_sync(0xFFFFFFFFu, rs0, 1);
    rs0 += __shfl_xor_sync(0xFFFFFFFFu, rs0, 2);
    rs1 += __shfl_xor_sync(0xFFFFFFFFu, rs1, 1);
    rs1 += __shfl_xor_sync(0xFFFFFFFFu, rs1, 2);
    const float inv0 = 1.f / rs0;
    const float inv1 = 1.f / rs1;

    // write O -> attnout[b][l][c]
#pragma unroll
    for (int nf2 = 0; nf2 < 4; ++nf2) {
        const int col = h * 32 + 8 * nf2 + 2 * lc;
        const size_t r0 = ((size_t)b * LDIM + i0 + lr) * CDIM + col;
        const size_t r1 = ((size_t)b * LDIM + i0 + lr + 8) * CDIM + col;
        *(float2*)&attnout[r0] = make_float2(o[nf2][0] * inv0, o[nf2][1] * inv0);
        *(float2*)&attnout[r1] = make_float2(o[nf2][2] * inv1, o[nf2][3] * inv1);
    }
}

// ---------------------------------------------------------------------------
extern "C" void kernel_launch(void* const* d_in, const int* in_sizes, int n_in,
                              void* d_out, int out_size)
{
    const float* x      = (const float*)d_in[0];
    const float* w_qkv  = (const float*)d_in[1];
    const float* b_qkv  = (const float*)d_in[2];
    const float* w_proj = (const float*)d_in[3];
    const float* b_proj = (const float*)d_in[4];
    float* out = (float*)d_out;

    float *qkv = nullptr, *attn = nullptr, *xt = nullptr, *kt = nullptr;
    cudaGetSymbolAddress((void**)&qkv, g_qkv);
    cudaGetSymbolAddress((void**)&attn, g_attn);
    cudaGetSymbolAddress((void**)&xt, g_xt);
    cudaGetSymbolAddress((void**)&kt, g_kt);

    const int SMEMSZ  = 4 * 128 * APITCH * 4;
    const int ASMEMSZ = ATTN_SMEM_FLOATS * 4;
    cudaFuncSetAttribute(gemm_mma<false>, cudaFuncAttributeMaxDynamicSharedMemorySize, SMEMSZ);
    cudaFuncSetAttribute(gemm_mma<true>,  cudaFuncAttributeMaxDynamicSharedMemorySize, SMEMSZ);
    cudaFuncSetAttribute(attn_mma, cudaFuncAttributeMaxDynamicSharedMemorySize, ASMEMSZ);

    // 1) transpose x -> xt[b][l][c]
    transpose_cl<<<dim3(LDIM / 32, CDIM / 32, BATCH), dim3(32, 8)>>>(x, xt);
    // 2) QKV GEMM (tf32 mma.sync): M=768, out [b][768][l]
    gemm_mma<false><<<dim3(LDIM / 128, 768 / 128, BATCH), 256, SMEMSZ>>>(w_qkv, xt, b_qkv, nullptr, qkv, 768);
    // 3) K transpose -> kt[bh][j][d]
    transpose_k<<<dim3(LDIM / 32, BATCH * 8), dim3(32, 8)>>>(qkv, kt);
    // 4) flash attention (tf32 mma.sync + ldmatrix), writes g_attn[b][l][c]
    attn_mma<<<dim3(64, LDIM / 64), 128, ASMEMSZ>>>(qkv, kt, attn);
    // 5) proj GEMM (tf32) + bias + residual
    gemm_mma<true><<<dim3(LDIM / 128, 256 / 128, BATCH), 256, SMEMSZ>>>(w_proj, attn, b_proj, x, out, 256);
}

// round 11
// speedup vs baseline: 3.6010x; 1.0365x over previous
#include <cuda_runtime.h>
#include <cstdint>

#define LDIM 1024   // h*w
#define CDIM 256
#define BATCH 8

// Scratch (no cudaMalloc allowed)
__device__ float g_qkv[BATCH * 3 * CDIM * LDIM];   // [b][768][l]
__device__ float g_attn[BATCH * LDIM * CDIM];      // [b][l][c]  (transposed)
__device__ float g_xt[BATCH * LDIM * CDIM];        // [b][l][c]  (transposed x)
__device__ float g_kt[BATCH * 8 * LDIM * 32];      // [bh][j][d] (K transposed)

// ---------- helpers ----------
__device__ __forceinline__ float ex2(float x) {
    float r; asm("ex2.approx.f32 %0, %1;" : "=f"(r) : "f"(x)); return r;
}
__device__ __forceinline__ void cp16(uint32_t smem, const void* gmem) {
    asm volatile("cp.async.ca.shared.global [%0], [%1], 16;" :: "r"(smem), "l"(gmem));
}
__device__ __forceinline__ void cp_commit() { asm volatile("cp.async.commit_group;"); }
template<int N> __device__ __forceinline__ void cp_wait() {
    asm volatile("cp.async.wait_group %0;" :: "n"(N));
}
__device__ __forceinline__ uint32_t s2u(const void* p) {
    uint32_t a;
    asm("{ .reg .u64 t; cvta.to.shared.u64 t, %1; cvt.u32.u64 %0, t; }" : "=r"(a) : "l"(p));
    return a;
}
__device__ __forceinline__ void ldsm4(uint32_t& r0, uint32_t& r1, uint32_t& r2, uint32_t& r3,
                                      uint32_t addr) {
    asm volatile("ldmatrix.sync.aligned.m8n8.x4.shared.b16 {%0,%1,%2,%3}, [%4];"
                 : "=r"(r0), "=r"(r1), "=r"(r2), "=r"(r3) : "r"(addr));
}

// ---------- mma.sync tf32 m16n8k8 ----------
__device__ __forceinline__ void mma_tf32(float* d, const uint32_t* a, const uint32_t* b) {
    asm volatile(
        "mma.sync.aligned.m16n8k8.row.col.f32.tf32.tf32.f32 "
        "{%0,%1,%2,%3}, {%4,%5,%6,%7}, {%8,%9}, {%0,%1,%2,%3};"
        : "+f"(d[0]), "+f"(d[1]), "+f"(d[2]), "+f"(d[3])
        : "r"(a[0]), "r"(a[1]), "r"(a[2]), "r"(a[3]), "r"(b[0]), "r"(b[1]));
}

// ---------------------------------------------------------------------------
// Transpose: x[b][c][l] -> xt[b][l][c]
// ---------------------------------------------------------------------------
__global__ __launch_bounds__(256)
void transpose_cl(const float* __restrict__ x, float* __restrict__ xt)
{
    __shared__ float tile[32][33];
    const int b  = blockIdx.z;
    const int c0 = blockIdx.y * 32;
    const int l0 = blockIdx.x * 32;
    const int tx = threadIdx.x, ty = threadIdx.y;   // 32 x 8
    const float* xb  = x  + (size_t)b * CDIM * LDIM;
    float*       xtb = xt + (size_t)b * LDIM * CDIM;
#pragma unroll
    for (int r = 0; r < 32; r += 8)
        tile[ty + r][tx] = xb[(size_t)(c0 + ty + r) * LDIM + l0 + tx];
    __syncthreads();
#pragma unroll
    for (int r = 0; r < 32; r += 8)
        xtb[(size_t)(l0 + ty + r) * CDIM + c0 + tx] = tile[tx][ty + r];
}

// ---------------------------------------------------------------------------
// K transpose: qkv K slice [d=32][l=1024] per (b,h) -> kt[bh][j=1024][d=32]
// ---------------------------------------------------------------------------
__global__ __launch_bounds__(256)
void transpose_k(const float* __restrict__ qkv, float* __restrict__ kt)
{
    __shared__ float tile[32][33];
    const int bh = blockIdx.y;
    const int b  = bh >> 3, h = bh & 7;
    const int l0 = blockIdx.x * 32;
    const int tx = threadIdx.x, ty = threadIdx.y;   // 32 x 8
    const float* Kp  = qkv + (size_t)(b * 768 + 256 + h * 32) * LDIM;
    float*       out = kt + (size_t)bh * LDIM * 32 + (size_t)l0 * 32;
#pragma unroll
    for (int r = 0; r < 32; r += 8)
        tile[ty + r][tx] = Kp[(size_t)(ty + r) * LDIM + l0 + tx];
    __syncthreads();
#pragma unroll
    for (int r = 0; r < 32; r += 8)
        out[(size_t)(ty + r) * 32 + tx] = tile[tx][ty + r];
}

// ---------------------------------------------------------------------------
// tf32 mma.sync GEMM (unchanged — validated rounds 8-10)
// ---------------------------------------------------------------------------
#define APITCH 36
template<bool RES>
__global__ __launch_bounds__(256)
void gemm_mma(const float* __restrict__ W, const float* __restrict__ Bm,
              const float* __restrict__ bias, const float* __restrict__ resid,
              float* __restrict__ out, int M)
{
    extern __shared__ float sm[];
    float (*As)[128][APITCH] = (float(*)[128][APITCH])sm;
    float (*Bs)[128][APITCH] = (float(*)[128][APITCH])(sm + 2 * 128 * APITCH);

    const int b    = blockIdx.z;
    const int o0   = blockIdx.y * 128;
    const int l0   = blockIdx.x * 128;
    const int t    = threadIdx.x;
    const int wid  = t >> 5, lane = t & 31;
    const int wm   = (wid & 1) * 64;
    const int wn   = (wid >> 1) * 32;
    const int lr   = lane >> 2;
    const int lc   = lane & 3;

    const float* Wp = W  + (size_t)o0 * CDIM;
    const float* Bp = Bm + (size_t)b * LDIM * CDIM + (size_t)l0 * CDIM;

    const uint32_t asm_b = s2u(sm);
    const uint32_t bsm_b = asm_b + 2u * 128u * APITCH * 4u;

    auto load_chunk = [&](int c, int st) {
        const uint32_t stoff = (uint32_t)st * 128u * APITCH * 4u;
#pragma unroll
        for (int r = 0; r < 4; ++r) {
            const int idx = r * 256 + t;
            const int row = idx >> 3;
            const int c4  = (idx & 7) * 4;
            const uint32_t so = stoff + (uint32_t)(row * APITCH + c4) * 4u;
            cp16(asm_b + so, Wp + (size_t)row * CDIM + c * 32 + c4);
            cp16(bsm_b + so, Bp + (size_t)row * CDIM + c * 32 + c4);
        }
    };

    float acc[4][4][4];
#pragma unroll
    for (int i = 0; i < 4; ++i)
#pragma unroll
        for (int j = 0; j < 4; ++j)
#pragma unroll
            for (int k = 0; k < 4; ++k) acc[i][j][k] = 0.f;

    load_chunk(0, 0);
    cp_commit();

    for (int c = 0; c < 8; ++c) {
        if (c + 1 < 8) load_chunk(c + 1, (c + 1) & 1);
        cp_commit();
        cp_wait<1>();
        __syncthreads();
        const int st = c & 1;

#pragma unroll
        for (int ks = 0; ks < 4; ++ks) {
            const int kc = ks * 8 + lc;
            uint32_t af[4][4];
#pragma unroll
            for (int mf = 0; mf < 4; ++mf) {
                const int r0 = wm + mf * 16 + lr;
                af[mf][0] = __float_as_uint(As[st][r0][kc]);
                af[mf][1] = __float_as_uint(As[st][r0 + 8][kc]);
                af[mf][2] = __float_as_uint(As[st][r0][kc + 4]);
                af[mf][3] = __float_as_uint(As[st][r0 + 8][kc + 4]);
            }
            uint32_t bf[4][2];
#pragma unroll
            for (int nf = 0; nf < 4; ++nf) {
                const int n = wn + nf * 8 + lr;
                bf[nf][0] = __float_as_uint(Bs[st][n][kc]);
                bf[nf][1] = __float_as_uint(Bs[st][n][kc + 4]);
            }
#pragma unroll
            for (int mf = 0; mf < 4; ++mf)
#pragma unroll
                for (int nf = 0; nf < 4; ++nf)
                    mma_tf32(acc[mf][nf], af[mf], bf[nf]);
        }
        __syncthreads();
    }

#pragma unroll
    for (int mf = 0; mf < 4; ++mf) {
        const int r0 = o0 + wm + mf * 16 + lr;
        const float b0 = __ldg(&bias[r0]);
        const float b1 = __ldg(&bias[r0 + 8]);
        const size_t ro0 = ((size_t)b * M + r0) * LDIM;
        const size_t ro1 = ((size_t)b * M + r0 + 8) * LDIM;
#pragma unroll
        for (int nf = 0; nf < 4; ++nf) {
            const int cc = l0 + wn + nf * 8 + 2 * lc;
            float2 v0 = make_float2(acc[mf][nf][0] + b0, acc[mf][nf][1] + b0);
            float2 v1 = make_float2(acc[mf][nf][2] + b1, acc[mf][nf][3] + b1);
            if (RES) {
                float2 x0 = *(const float2*)&resid[ro0 + cc];
                float2 x1 = *(const float2*)&resid[ro1 + cc];
                v0.x += x0.x; v0.y += x0.y; v1.x += x1.x; v1.y += x1.y;
            }
            *(float2*)&out[ro0 + cc] = v0;
            *(float2*)&out[ro1 + cc] = v1;
        }
    }
}

// ---------------------------------------------------------------------------
// Flash attention v2: warp owns 32 query rows (2 row-halves); B-fragments
// (K for QK, V for PV) reused across both halves -> ldsm4/query drops 40%.
// CTA = 64 threads (2 warps) = 64 queries; key-tile 32, double-buffered;
// grid 1024, 7 CTAs/SM (smem 27.6KB, regs capped 144) -> single wave.
// Pitches 36 (9 mod 8 = 1): conflict-free ldmatrix rows.
// ---------------------------------------------------------------------------
#define TP 36
__global__ __launch_bounds__(64, 7)
void attn_mma(const float* __restrict__ qkv, const float* __restrict__ kt,
              float* __restrict__ attnout)
{
    __shared__ __align__(16) float KS[2][32][TP];   // [st][j][d]
    __shared__ __align__(16) float VS[2][32][TP];   // [st][d][j]
    __shared__ __align__(16) float PSm[2][32][TP];  // [warp][i][j]

    const int bh   = blockIdx.x;
    const int b    = bh >> 3;
    const int h    = bh & 7;
    const int qt   = blockIdx.y;
    const int t    = threadIdx.x;
    const int wid  = t >> 5, lane = t & 31;
    const int lr   = lane >> 2;   // 0..7
    const int lc   = lane & 3;    // 0..3

    float (*PS)[TP] = PSm[wid];

    const float* Qp  = qkv + (size_t)(b * 768 + h * 32) * LDIM;
    const float* Vp  = qkv + (size_t)(b * 768 + 512 + h * 32) * LDIM;
    const float* Ktp = kt + (size_t)bh * LDIM * 32;

    const float S = 0.17677669529663687f * 1.4426950408889634f;  // dh^-0.5 * log2e

    const int i0 = qt * 64 + wid * 32;

    // Q fragments for both row-halves (persistent)
    uint32_t qf[2][4][4];
#pragma unroll
    for (int rh = 0; rh < 2; ++rh) {
        const int iq = i0 + rh * 16;
#pragma unroll
        for (int ks = 0; ks < 4; ++ks) {
            const int d0 = 8 * ks + lc;
            qf[rh][ks][0] = __float_as_uint(Qp[(size_t)d0 * LDIM + iq + lr] * S);
            qf[rh][ks][1] = __float_as_uint(Qp[(size_t)d0 * LDIM + iq + lr + 8] * S);
            qf[rh][ks][2] = __float_as_uint(Qp[(size_t)(d0 + 4) * LDIM + iq + lr] * S);
            qf[rh][ks][3] = __float_as_uint(Qp[(size_t)(d0 + 4) * LDIM + iq + lr + 8] * S);
        }
    }

    float o[2][4][4];
#pragma unroll
    for (int rh = 0; rh < 2; ++rh)
#pragma unroll
        for (int i = 0; i < 4; ++i)
#pragma unroll
            for (int j = 0; j < 4; ++j) o[rh][i][j] = 0.f;
    float rsA[2] = {0.f, 0.f}, rsB[2] = {0.f, 0.f};

    const uint32_t ks_u[2] = { s2u(&KS[0][0][0]), s2u(&KS[1][0][0]) };
    const uint32_t vs_u[2] = { s2u(&VS[0][0][0]), s2u(&VS[1][0][0]) };
    const uint32_t ps_u    = s2u(&PS[0][0]);

    // per-lane ldmatrix address components (elements)
    const int mi = lane >> 3;            // matrix index 0..3
    const int mr = lane & 7;             // row within matrix
    const uint32_t qk_lm = (uint32_t)((((mi >> 1) * 8 + mr) * TP + (mi & 1) * 4) * 4);
    const uint32_t pa_lm = ps_u + (uint32_t)((((mi & 1) * 8 + mr) * TP + (mi >> 1) * 4) * 4);
    const uint32_t pv_lm = (uint32_t)((mr * TP + mi * 4) * 4);

    // tile copier: 32x32 K + 32x32 V, 64 threads x 4 chunks each
    auto copy_tile = [&](int st, int j0) {
#pragma unroll
        for (int r = 0; r < 4; ++r) {
            const int idx = r * 64 + t;          // 0..255
            const int row = idx >> 3;            // 0..31
            const int ch  = (idx & 7) * 4;       // 0..28
            cp16(ks_u[st] + (uint32_t)(row * TP + ch) * 4u,
                 Ktp + (size_t)(j0 + row) * 32 + ch);
            cp16(vs_u[st] + (uint32_t)(row * TP + ch) * 4u,
                 Vp + (size_t)row * LDIM + j0 + ch);
        }
    };

    copy_tile(0, 0);
    cp_commit();

    for (int jt = 0; jt < 32; ++jt) {
        const int st = jt & 1;
        if (jt < 31) copy_tile(st ^ 1, (jt + 1) * 32);
        cp_commit();
        cp_wait<1>();
        __syncthreads();

        // ---- QK: S[32 rows][32 keys]; B-frags shared across row-halves ----
        float c[2][4][4];
#pragma unroll
        for (int rh = 0; rh < 2; ++rh)
#pragma unroll
            for (int nf = 0; nf < 4; ++nf)
#pragma unroll
                for (int k = 0; k < 4; ++k) c[rh][nf][k] = 0.f;

#pragma unroll
        for (int ks = 0; ks < 4; ++ks) {
#pragma unroll
            for (int g = 0; g < 2; ++g) {        // nf = 2g, 2g+1
                uint32_t b0, b1, b2, b3;
                ldsm4(b0, b1, b2, b3,
                      ks_u[st] + qk_lm + (uint32_t)((g * 16 * TP + ks * 8) * 4));
                uint32_t bfA[2] = { b0, b1 }, bfB[2] = { b2, b3 };
                mma_tf32(c[0][2 * g],     qf[0][ks], bfA);
                mma_tf32(c[0][2 * g + 1], qf[0][ks], bfB);
                mma_tf32(c[1][2 * g],     qf[1][ks], bfA);
                mma_tf32(c[1][2 * g + 1], qf[1][ks], bfB);
            }
        }

        // ---- exp2 + row sums + stage P ----
#pragma unroll
        for (int rh = 0; rh < 2; ++rh) {
#pragma unroll
            for (int nf = 0; nf < 4; ++nf) {
                const float p0 = ex2(c[rh][nf][0]), p1 = ex2(c[rh][nf][1]);
                const float p2 = ex2(c[rh][nf][2]), p3 = ex2(c[rh][nf][3]);
                rsA[rh] += p0 + p1;
                rsB[rh] += p2 + p3;
                *(float2*)&PS[rh * 16 + lr][8 * nf + 2 * lc]     = make_float2(p0, p1);
                *(float2*)&PS[rh * 16 + lr + 8][8 * nf + 2 * lc] = make_float2(p2, p3);
            }
        }
        __syncwarp();

        // ---- PV: O[32 rows][32 d] += P * V; V B-frags shared across halves ----
#pragma unroll
        for (int kp = 0; kp < 2; ++kp) {         // ks2 = 2kp, 2kp+1
            uint32_t A00[4], A01[4], A10[4], A11[4];
            ldsm4(A00[0], A00[1], A00[2], A00[3],
                  pa_lm + (uint32_t)(((2 * kp) * 8) * 4));
            ldsm4(A01[0], A01[1], A01[2], A01[3],
                  pa_lm + (uint32_t)(((2 * kp + 1) * 8) * 4));
            ldsm4(A10[0], A10[1], A10[2], A10[3],
                  pa_lm + (uint32_t)((16 * TP + (2 * kp) * 8) * 4));
            ldsm4(A11[0], A11[1], A11[2], A11[3],
                  pa_lm + (uint32_t)((16 * TP + (2 * kp + 1) * 8) * 4));
#pragma unroll
            for (int nf2 = 0; nf2 < 4; ++nf2) {
                uint32_t v0, v1, v2, v3;
                ldsm4(v0, v1, v2, v3,
                      vs_u[st] + pv_lm + (uint32_t)((nf2 * 8 * TP + kp * 16) * 4));
                uint32_t bfA[2] = { v0, v1 }, bfB[2] = { v2, v3 };
                mma_tf32(o[0][nf2], A00, bfA);
                mma_tf32(o[0][nf2], A01, bfB);
                mma_tf32(o[1][nf2], A10, bfA);
                mma_tf32(o[1][nf2], A11, bfB);
            }
        }
        __syncthreads();
    }

    // quad-reduce row sums, normalize, write [b][l][c]
#pragma unroll
    for (int rh = 0; rh < 2; ++rh) {
        float r0 = rsA[rh], r1 = rsB[rh];
        r0 += __shfl_xor_sync(0xFFFFFFFFu, r0, 1);
        r0 += __shfl_xor_sync(0xFFFFFFFFu, r0, 2);
        r1 += __shfl_xor_sync(0xFFFFFFFFu, r1, 1);
        r1 += __shfl_xor_sync(0xFFFFFFFFu, r1, 2);
        const float inv0 = 1.f / r0;
        const float inv1 = 1.f / r1;
        const int iq = i0 + rh * 16;
#pragma unroll
        for (int nf2 = 0; nf2 < 4; ++nf2) {
            const int col = h * 32 + 8 * nf2 + 2 * lc;
            const size_t w0 = ((size_t)b * LDIM + iq + lr) * CDIM + col;
            const size_t w1 = ((size_t)b * LDIM + iq + lr + 8) * CDIM + col;
            *(float2*)&attnout[w0] = make_float2(o[rh][nf2][0] * inv0, o[rh][nf2][1] * inv0);
            *(float2*)&attnout[w1] = make_float2(o[rh][nf2][2] * inv1, o[rh][nf2][3] * inv1);
        }
    }
}

// ---------------------------------------------------------------------------
extern "C" void kernel_launch(void* const* d_in, const int* in_sizes, int n_in,
                              void* d_out, int out_size)
{
    const float* x      = (const float*)d_in[0];
    const float* w_qkv  = (const float*)d_in[1];
    const float* b_qkv  = (const float*)d_in[2];
    const float* w_proj = (const float*)d_in[3];
    const float* b_proj = (const float*)d_in[4];
    float* out = (float*)d_out;

    float *qkv = nullptr, *attn = nullptr, *xt = nullptr, *kt = nullptr;
    cudaGetSymbolAddress((void**)&qkv, g_qkv);
    cudaGetSymbolAddress((void**)&attn, g_attn);
    cudaGetSymbolAddress((void**)&xt, g_xt);
    cudaGetSymbolAddress((void**)&kt, g_kt);

    const int SMEMSZ = 4 * 128 * APITCH * 4;
    cudaFuncSetAttribute(gemm_mma<false>, cudaFuncAttributeMaxDynamicSharedMemorySize, SMEMSZ);
    cudaFuncSetAttribute(gemm_mma<true>,  cudaFuncAttributeMaxDynamicSharedMemorySize, SMEMSZ);

    // 1) transpose x -> xt[b][l][c]
    transpose_cl<<<dim3(LDIM / 32, CDIM / 32, BATCH), dim3(32, 8)>>>(x, xt);
    // 2) QKV GEMM (tf32 mma.sync): M=768, out [b][768][l]
    gemm_mma<false><<<dim3(LDIM / 128, 768 / 128, BATCH), 256, SMEMSZ>>>(w_qkv, xt, b_qkv, nullptr, qkv, 768);
    // 3) K transpose -> kt[bh][j][d]
    transpose_k<<<dim3(LDIM / 32, BATCH * 8), dim3(32, 8)>>>(qkv, kt);
    // 4) flash attention v2 (tf32 mma.sync + ldmatrix, 32 rows/warp)
    attn_mma<<<dim3(64, LDIM / 64), 64>>>(qkv, kt, attn);
    // 5) proj GEMM (tf32) + bias + residual
    gemm_mma<true><<<dim3(LDIM / 128, 256 / 128, BATCH), 256, SMEMSZ>>>(w_proj, attn, b_proj, x, out, 256);
}